// round 1
// baseline (speedup 1.0000x reference)
#include <cuda_runtime.h>

#define NEPS 1e-20f

static constexpr int BB = 16;
static constexpr int H0 = 512, W0 = 640;
static constexpr int FULLN  = BB * 2 * H0 * W0;            // 10,485,760
static constexpr int HALFN  = BB * 2 * (H0/2) * (W0/2);    //  2,621,440
static constexpr int QUARTN = BB * 2 * (H0/4) * (W0/4);    //    655,360
static constexpr int EIGHTN = BB * 2 * (H0/8) * (W0/8);    //    163,840

// Scratch (static __device__ — no allocation APIs allowed)
__device__ float g_fx_a[FULLN];
__device__ float g_fc_a[FULLN];
__device__ float g_fx_b[FULLN];
__device__ float g_fc_b[FULLN];
__device__ float g_hx_a[HALFN];
__device__ float g_hc_a[HALFN];
__device__ float g_hx_b[HALFN];
__device__ float g_hc_b[HALFN];
__device__ float g_qx_a[QUARTN];
__device__ float g_qc_a[QUARTN];
__device__ float g_qx_b[QUARTN];
__device__ float g_qc_b[QUARTN];
__device__ float g_ex_a[EIGHTN];
__device__ float g_ec_a[EIGHTN];
__device__ float g_ex_b[EIGHTN];
__device__ float g_ec_b[EIGHTN];

// ---------------------------------------------------------------------------
// navg kernel: 'same' KxK conv of (x*c) and c, CO=2 outputs:
//   ca   = conv(c, w)
//   xout = conv(x*c, w) / (ca + EPS) + b
//   cout = ca / sum(w)
// Optional fused 2x2 argmax pool (argmax of cout picks, c/=4).
// One thread computes a 2x2 quad (== one pool block). Tile = 32x32 outputs.
// ---------------------------------------------------------------------------
template<int CI, int K, bool POOL>
__global__ void __launch_bounds__(256, 2)
navg_kernel(const float* __restrict__ xin, const float* __restrict__ cin,
            const float* __restrict__ w,   const float* __restrict__ bias,
            float* __restrict__ xout, float* __restrict__ cout,
            float* __restrict__ xpool, float* __restrict__ cpool,
            int H, int W)
{
    constexpr int CO   = 2;
    constexpr int HALO = K / 2;
    constexpr int SH   = 32 + K - 1;
    constexpr int SW   = 32 + K - 1;
    constexpr int SWP  = (SW & 1) ? SW : SW + 1;   // odd stride -> conflict-free

    __shared__ float sc [CI][SH][SWP];
    __shared__ float sxc[CI][SH][SWP];
    __shared__ float swt[CO * CI * K * K];
    __shared__ float srs[CO], sb[CO];

    const int tx  = threadIdx.x, ty = threadIdx.y;
    const int tid = ty * 16 + tx;
    const int b   = blockIdx.z;
    const int gx0 = blockIdx.x * 32 - HALO;
    const int gy0 = blockIdx.y * 32 - HALO;

    for (int i = tid; i < CO * CI * K * K; i += 256) swt[i] = w[i];
    if (tid < CO) {
        float s = 0.f;
        #pragma unroll 1
        for (int i = 0; i < CI * K * K; i++) s += w[tid * CI * K * K + i];
        srs[tid] = 1.f / s;
        sb[tid]  = bias[tid];
    }

    for (int i = tid; i < CI * SH * SW; i += 256) {
        int ci  = i / (SH * SW);
        int rem = i % (SH * SW);
        int ly  = rem / SW;
        int lx  = rem % SW;
        int gy = gy0 + ly, gx = gx0 + lx;
        float cv = 0.f, xv = 0.f;
        if (gy >= 0 && gy < H && gx >= 0 && gx < W) {
            int off = ((b * CI + ci) * H + gy) * W + gx;
            cv = cin[off];
            xv = xin[off];
        }
        sc [ci][ly][lx] = cv;
        sxc[ci][ly][lx] = xv * cv;
    }
    __syncthreads();

    float xa[2][2][CO] = {};
    float ca[2][2][CO] = {};

    #pragma unroll
    for (int ci = 0; ci < CI; ci++) {
        #pragma unroll
        for (int r = 0; r <= K; r++) {        // K+1 input rows for the quad
            float vx[K + 1], vc[K + 1];
            #pragma unroll
            for (int j = 0; j <= K; j++) {
                vx[j] = sxc[ci][2 * ty + r][2 * tx + j];
                vc[j] = sc [ci][2 * ty + r][2 * tx + j];
            }
            #pragma unroll
            for (int ky = 0; ky < K; ky++) {
                const int oy = r - ky;
                if (oy < 0 || oy > 1) continue;   // compile-time pruned
                #pragma unroll
                for (int kx = 0; kx < K; kx++) {
                    #pragma unroll
                    for (int co = 0; co < CO; co++) {
                        float wv = swt[((co * CI + ci) * K + ky) * K + kx];
                        xa[oy][0][co] += wv * vx[kx];
                        xa[oy][1][co] += wv * vx[kx + 1];
                        ca[oy][0][co] += wv * vc[kx];
                        ca[oy][1][co] += wv * vc[kx + 1];
                    }
                }
            }
        }
    }

    const int oy0 = blockIdx.y * 32 + 2 * ty;
    const int ox0 = blockIdx.x * 32 + 2 * tx;

    float xov[2][2][CO], cov[2][2][CO];
    #pragma unroll
    for (int dy = 0; dy < 2; dy++)
        #pragma unroll
        for (int dx = 0; dx < 2; dx++)
            #pragma unroll
            for (int co = 0; co < CO; co++) {
                float cav = ca[dy][dx][co];
                xov[dy][dx][co] = __fdividef(xa[dy][dx][co], cav + NEPS) + sb[co];
                cov[dy][dx][co] = cav * srs[co];
            }

    #pragma unroll
    for (int dy = 0; dy < 2; dy++)
        #pragma unroll
        for (int dx = 0; dx < 2; dx++) {
            int y = oy0 + dy, x = ox0 + dx;
            if (y < H && x < W) {
                #pragma unroll
                for (int co = 0; co < CO; co++) {
                    int off = ((b * 2 + co) * H + y) * W + x;
                    xout[off] = xov[dy][dx][co];
                    cout[off] = cov[dy][dx][co];
                }
            }
        }

    if (POOL) {
        if (oy0 < H && ox0 < W) {
            #pragma unroll
            for (int co = 0; co < CO; co++) {
                float bc = cov[0][0][co], bx = xov[0][0][co];
                if (cov[0][1][co] > bc) { bc = cov[0][1][co]; bx = xov[0][1][co]; }
                if (cov[1][0][co] > bc) { bc = cov[1][0][co]; bx = xov[1][0][co]; }
                if (cov[1][1][co] > bc) { bc = cov[1][1][co]; bx = xov[1][1][co]; }
                int off = ((b * 2 + co) * (H >> 1) + (oy0 >> 1)) * (W >> 1) + (ox0 >> 1);
                cpool[off] = bc * 0.25f;
                xpool[off] = bx;
            }
        }
    }
}

// ---------------------------------------------------------------------------
// concat(2ch src1, 2ch src2) -> 3x3 navg, CO=2. Each source may be half-res
// (shift=1): nearest 2x upsample is fused into the tile loader via >>shift.
// FINAL: additionally fuse the trailing 1x1 navg (w4,b4) and write the two
// single-channel outputs (xout, cout) back-to-back into d_out.
// ---------------------------------------------------------------------------
template<bool FINAL>
__global__ void __launch_bounds__(256, 2)
navg_cat_kernel(const float* __restrict__ x1, const float* __restrict__ c1, int sh1,
                const float* __restrict__ x2, const float* __restrict__ c2, int sh2,
                const float* __restrict__ w,  const float* __restrict__ bias,
                const float* __restrict__ w4, const float* __restrict__ b4,
                float* __restrict__ xout, float* __restrict__ cout,
                int H, int W)
{
    constexpr int CI = 4, CO = 2, K = 3;
    constexpr int HALO = 1;
    constexpr int SH = 34, SW = 34, SWP = 35;

    __shared__ float sc [CI][SH][SWP];
    __shared__ float sxc[CI][SH][SWP];
    __shared__ float swt[CO * CI * K * K];
    __shared__ float srs[CO], sb[CO];
    __shared__ float sw4[2], sb4[1], srs4[1];

    const int tx  = threadIdx.x, ty = threadIdx.y;
    const int tid = ty * 16 + tx;
    const int b   = blockIdx.z;
    const int gx0 = blockIdx.x * 32 - HALO;
    const int gy0 = blockIdx.y * 32 - HALO;

    for (int i = tid; i < CO * CI * K * K; i += 256) swt[i] = w[i];
    if (tid < CO) {
        float s = 0.f;
        #pragma unroll 1
        for (int i = 0; i < CI * K * K; i++) s += w[tid * CI * K * K + i];
        srs[tid] = 1.f / s;
        sb[tid]  = bias[tid];
    }
    if (FINAL && tid == 0) {
        sw4[0] = w4[0]; sw4[1] = w4[1];
        sb4[0] = b4[0];
        srs4[0] = 1.f / (w4[0] + w4[1]);
    }

    for (int i = tid; i < CI * SH * SW; i += 256) {
        int ci  = i / (SH * SW);
        int rem = i % (SH * SW);
        int ly  = rem / SW;
        int lx  = rem % SW;
        int gy = gy0 + ly, gx = gx0 + lx;
        const float* xs; const float* cs; int sh;
        if (ci < 2) { xs = x1; cs = c1; sh = sh1; }
        else        { xs = x2; cs = c2; sh = sh2; }
        int cc = ci & 1;
        float cv = 0.f, xv = 0.f;
        if (gy >= 0 && gy < H && gx >= 0 && gx < W) {
            int Hs = H >> sh, Ws = W >> sh;
            int off = ((b * 2 + cc) * Hs + (gy >> sh)) * Ws + (gx >> sh);
            cv = cs[off];
            xv = xs[off];
        }
        sc [ci][ly][lx] = cv;
        sxc[ci][ly][lx] = xv * cv;
    }
    __syncthreads();

    float xa[2][2][CO] = {};
    float ca[2][2][CO] = {};

    #pragma unroll
    for (int ci = 0; ci < CI; ci++) {
        #pragma unroll
        for (int r = 0; r <= K; r++) {
            float vx[K + 1], vc[K + 1];
            #pragma unroll
            for (int j = 0; j <= K; j++) {
                vx[j] = sxc[ci][2 * ty + r][2 * tx + j];
                vc[j] = sc [ci][2 * ty + r][2 * tx + j];
            }
            #pragma unroll
            for (int ky = 0; ky < K; ky++) {
                const int oy = r - ky;
                if (oy < 0 || oy > 1) continue;
                #pragma unroll
                for (int kx = 0; kx < K; kx++) {
                    #pragma unroll
                    for (int co = 0; co < CO; co++) {
                        float wv = swt[((co * CI + ci) * K + ky) * K + kx];
                        xa[oy][0][co] += wv * vx[kx];
                        xa[oy][1][co] += wv * vx[kx + 1];
                        ca[oy][0][co] += wv * vc[kx];
                        ca[oy][1][co] += wv * vc[kx + 1];
                    }
                }
            }
        }
    }

    const int oy0 = blockIdx.y * 32 + 2 * ty;
    const int ox0 = blockIdx.x * 32 + 2 * tx;

    #pragma unroll
    for (int dy = 0; dy < 2; dy++)
        #pragma unroll
        for (int dx = 0; dx < 2; dx++) {
            int y = oy0 + dy, x = ox0 + dx;
            if (y >= H || x >= W) continue;

            float xo_[CO], co_[CO];
            #pragma unroll
            for (int co = 0; co < CO; co++) {
                float cav = ca[dy][dx][co];
                xo_[co] = __fdividef(xa[dy][dx][co], cav + NEPS) + sb[co];
                co_[co] = cav * srs[co];
            }

            if (FINAL) {
                // fused trailing 1x1 navg (w4, b4), 2ch -> 1ch
                float a4 = sw4[0] * co_[0] + sw4[1] * co_[1];
                float xn = sw4[0] * (xo_[0] * co_[0]) + sw4[1] * (xo_[1] * co_[1]);
                float xf = __fdividef(xn, a4 + NEPS) + sb4[0];
                float cf = a4 * srs4[0];
                int off = (b * H + y) * W + x;
                xout[off] = xf;   // xout plane
                cout[off] = cf;   // cout plane (d_out + B*H*W)
            } else {
                #pragma unroll
                for (int co = 0; co < CO; co++) {
                    int off = ((b * 2 + co) * H + y) * W + x;
                    xout[off] = xo_[co];
                    cout[off] = co_[co];
                }
            }
        }
}

// ---------------------------------------------------------------------------
extern "C" void kernel_launch(void* const* d_in, const int* in_sizes, int n_in,
                              void* d_out, int out_size)
{
    (void)in_sizes; (void)n_in;
    const float* x0  = (const float*)d_in[0];
    const float* c0  = (const float*)d_in[1];
    const float* w1  = (const float*)d_in[2];
    const float* w2  = (const float*)d_in[3];
    const float* w3  = (const float*)d_in[4];
    const float* w4  = (const float*)d_in[5];
    const float* w34 = (const float*)d_in[6];
    const float* w23 = (const float*)d_in[7];
    const float* w12 = (const float*)d_in[8];
    const float* b1  = (const float*)d_in[9];
    const float* b2  = (const float*)d_in[10];
    const float* b3  = (const float*)d_in[11];
    const float* b4  = (const float*)d_in[12];
    const float* b34 = (const float*)d_in[13];
    const float* b23 = (const float*)d_in[14];
    const float* b12 = (const float*)d_in[15];
    float* outp = (float*)d_out;
    (void)out_size;

    float *fx_a, *fc_a, *fx_b, *fc_b;
    float *hx_a, *hc_a, *hx_b, *hc_b;
    float *qx_a, *qc_a, *qx_b, *qc_b;
    float *ex_a, *ec_a, *ex_b, *ec_b;
    cudaGetSymbolAddress((void**)&fx_a, g_fx_a);
    cudaGetSymbolAddress((void**)&fc_a, g_fc_a);
    cudaGetSymbolAddress((void**)&fx_b, g_fx_b);
    cudaGetSymbolAddress((void**)&fc_b, g_fc_b);
    cudaGetSymbolAddress((void**)&hx_a, g_hx_a);
    cudaGetSymbolAddress((void**)&hc_a, g_hc_a);
    cudaGetSymbolAddress((void**)&hx_b, g_hx_b);
    cudaGetSymbolAddress((void**)&hc_b, g_hc_b);
    cudaGetSymbolAddress((void**)&qx_a, g_qx_a);
    cudaGetSymbolAddress((void**)&qc_a, g_qc_a);
    cudaGetSymbolAddress((void**)&qx_b, g_qx_b);
    cudaGetSymbolAddress((void**)&qc_b, g_qc_b);
    cudaGetSymbolAddress((void**)&ex_a, g_ex_a);
    cudaGetSymbolAddress((void**)&ec_a, g_ec_a);
    cudaGetSymbolAddress((void**)&ex_b, g_ex_b);
    cudaGetSymbolAddress((void**)&ec_b, g_ec_b);

    dim3 blk(16, 16);
    auto grd = [](int W, int H) { return dim3((W + 31) / 32, (H + 31) / 32, BB); };

    // L1: navg(w1, c0, x0)            full res, CI=1
    navg_kernel<1, 5, false><<<grd(640, 512), blk>>>(
        x0, c0, w1, b1, fx_a, fc_a, nullptr, nullptr, 512, 640);
    // L2: navg(w2)                     full
    navg_kernel<2, 5, false><<<grd(640, 512), blk>>>(
        fx_a, fc_a, w2, b2, fx_b, fc_b, nullptr, nullptr, 512, 640);
    // L3: navg(w3)  -> (x1,c1)=fa  + fused pool -> ha = (x1_ds,c1_ds)
    navg_kernel<2, 5, true><<<grd(640, 512), blk>>>(
        fx_b, fc_b, w3, b3, fx_a, fc_a, hx_a, hc_a, 512, 640);
    // L5: navg(w2)                     half
    navg_kernel<2, 5, false><<<grd(320, 256), blk>>>(
        hx_a, hc_a, w2, b2, hx_b, hc_b, nullptr, nullptr, 256, 320);
    // L6: navg(w3) -> (x2_ds,c2_ds)=ha + pool -> qa = (x2_dss,c2_dss)
    navg_kernel<2, 5, true><<<grd(320, 256), blk>>>(
        hx_b, hc_b, w3, b3, hx_a, hc_a, qx_a, qc_a, 256, 320);
    // L8: navg(w2) -> (x3_ds,c3_ds)=qb + pool -> ea = (x3_dss,c3_dss)
    navg_kernel<2, 5, true><<<grd(160, 128), blk>>>(
        qx_a, qc_a, w2, b2, qx_b, qc_b, ex_a, ec_a, 128, 160);
    // L10: navg(w2) -> (x4_ds,c4_ds)=eb     eighth
    navg_kernel<2, 5, false><<<grd(80, 64), blk>>>(
        ex_a, ec_a, w2, b2, ex_b, ec_b, nullptr, nullptr, 64, 80);
    // L12: navg(w34, cat(c3_ds, up2(c4_ds))) -> qa = (x34_ds,c34_ds)  quarter
    navg_cat_kernel<false><<<grd(160, 128), blk>>>(
        qx_b, qc_b, 0, ex_b, ec_b, 1, w34, b34, nullptr, nullptr,
        qx_a, qc_a, 128, 160);
    // L14: navg(w23, cat(c2_ds, up2(c34_ds))) -> hb = (x23_ds,c23_ds)  half
    navg_cat_kernel<false><<<grd(320, 256), blk>>>(
        hx_a, hc_a, 0, qx_a, qc_a, 1, w23, b23, nullptr, nullptr,
        hx_b, hc_b, 256, 320);
    // L16+L17: navg(w12, cat(up2(c23), c1)) then fused 1x1 navg(w4) -> d_out
    navg_cat_kernel<true><<<grd(640, 512), blk>>>(
        hx_b, hc_b, 1, fx_a, fc_a, 0, w12, b12, w4, b4,
        outp, outp + (size_t)BB * H0 * W0, 512, 640);
}

// round 2
// speedup vs baseline: 1.3872x; 1.3872x over previous
#include <cuda_runtime.h>

#define NEPS 1e-20f

static constexpr int BB = 16;
static constexpr int H0 = 512, W0 = 640;
static constexpr int FULLN  = BB * 2 * H0 * W0;
static constexpr int HALFN  = BB * 2 * (H0/2) * (W0/2);
static constexpr int QUARTN = BB * 2 * (H0/4) * (W0/4);
static constexpr int EIGHTN = BB * 2 * (H0/8) * (W0/8);

// Scratch (static __device__ — no allocation APIs allowed)
__device__ float g_fx_a[FULLN];
__device__ float g_fc_a[FULLN];
__device__ float g_fx_b[FULLN];
__device__ float g_fc_b[FULLN];
__device__ float g_hx_a[HALFN];
__device__ float g_hc_a[HALFN];
__device__ float g_hx_b[HALFN];
__device__ float g_hc_b[HALFN];
__device__ float g_qx_a[QUARTN];
__device__ float g_qc_a[QUARTN];
__device__ float g_qx_b[QUARTN];
__device__ float g_qc_b[QUARTN];
__device__ float g_ex_a[EIGHTN];
__device__ float g_ec_a[EIGHTN];
__device__ float g_ex_b[EIGHTN];
__device__ float g_ec_b[EIGHTN];

// Packed duplicated weights (w,w) as 64-bit lanes. Layout (float offsets/pairs):
//   w1:0(50) w2:50(100) w3:150(100) w34:250(72) w23:322(72) w12:394(72) w4:466(2)
__constant__ unsigned long long g_wc[512];
__device__   unsigned long long g_wstage[512];
__device__   float2             g_brs[16];   // (bias, 1/sum(w)) per (layer, co)

__device__ __forceinline__ void ffma2(unsigned long long& a,
                                      unsigned long long w,
                                      unsigned long long v) {
    asm("fma.rn.f32x2 %0, %1, %2, %0;" : "+l"(a) : "l"(w), "l"(v));
}
__device__ __forceinline__ float2 unpk(unsigned long long v) {
    float2 r;
    asm("mov.b64 {%0, %1}, %2;" : "=f"(r.x), "=f"(r.y) : "l"(v));
    return r;
}

// ---------------------------------------------------------------------------
// prep: duplicate weights into 64-bit (w,w) lanes; compute (bias, 1/sum(w)).
// ---------------------------------------------------------------------------
__global__ void prep_kernel(
    const float* __restrict__ w1,  const float* __restrict__ w2,
    const float* __restrict__ w3,  const float* __restrict__ w34,
    const float* __restrict__ w23, const float* __restrict__ w12,
    const float* __restrict__ w4,
    const float* __restrict__ b1,  const float* __restrict__ b2,
    const float* __restrict__ b3,  const float* __restrict__ b34,
    const float* __restrict__ b23, const float* __restrict__ b12,
    const float* __restrict__ b4)
{
    const float* ws[7] = {w1, w2, w3, w34, w23, w12, w4};
    const int off[8]   = {0, 50, 150, 250, 322, 394, 466, 468};
    int t = threadIdx.x;
    for (int i = t; i < 468; i += blockDim.x) {
        int L = 0;
        while (i >= off[L + 1]) L++;
        unsigned int u = __float_as_uint(ws[L][i - off[L]]);
        g_wstage[i] = (unsigned long long)u * 0x100000001ULL;  // (w,w)
    }
    if (t < 13) {   // 6 layers x 2 co + w4 (co=0 only)
        int L = t >> 1, co = t & 1;
        const int cnt[7] = {25, 50, 50, 36, 36, 36, 2};  // CI*K*K per co
        const float* bs[7] = {b1, b2, b3, b34, b23, b12, b4};
        float s = 0.f;
        const float* wp = ws[L] + co * cnt[L];
        for (int i = 0; i < cnt[L]; i++) s += wp[i];
        g_brs[t] = make_float2(bs[L][co], 1.f / s);
    }
}

// ---------------------------------------------------------------------------
// 5x5 navg, CO=2. Interleaved (x*c, c) float2 tiles in smem; packed f32x2
// accumulation so one FMA updates both the x-numerator and the c-denominator.
// Thread micro-tile: 2 wide x 4 tall (two 2x2 pool blocks). Block: 32x64 out.
// ---------------------------------------------------------------------------
template<int CI, bool POOL>
__global__ void __launch_bounds__(256, 2)
navg5(const float* __restrict__ xin, const float* __restrict__ cin,
      int woff, int brsoff,
      float* __restrict__ xout, float* __restrict__ cout,
      float* __restrict__ xpool, float* __restrict__ cpool,
      int H, int W)
{
    constexpr int SH = 68, SW = 36;   // 64+4 rows, 32+4 pair-cols
    __shared__ __align__(16) unsigned long long sm[CI][SH][SW];

    const int tid = threadIdx.x;
    const int tx  = tid & 15, ty = tid >> 4;
    const int b   = blockIdx.z;
    const int gx0 = blockIdx.x * 32 - 2;
    const int gy0 = blockIdx.y * 64 - 2;

    float2* smf = (float2*)sm;
    for (int i = tid; i < CI * SH * SW; i += 256) {
        int ci = i / (SH * SW), rem = i % (SH * SW);
        int ly = rem / SW, lx = rem % SW;
        int gy = gy0 + ly, gx = gx0 + lx;
        float cv = 0.f, xv = 0.f;
        if ((unsigned)gy < (unsigned)H && (unsigned)gx < (unsigned)W) {
            int o = ((b * CI + ci) * H + gy) * W + gx;
            cv = cin[o];
            xv = xin[o];
        }
        smf[i] = make_float2(xv * cv, cv);
    }
    __syncthreads();

    unsigned long long acc[4][2][2];   // [oy][xpos][co], lanes = (xa, ca)
    #pragma unroll
    for (int i = 0; i < 4; i++)
        #pragma unroll
        for (int j = 0; j < 2; j++)
            #pragma unroll
            for (int k = 0; k < 2; k++) acc[i][j][k] = 0ULL;

    #pragma unroll
    for (int ci = 0; ci < CI; ci++) {
        #pragma unroll
        for (int r = 0; r < 8; r++) {
            const unsigned long long* rp = &sm[ci][4 * ty + r][2 * tx];
            ulonglong2 p0 = *(const ulonglong2*)rp;
            ulonglong2 p1 = *(const ulonglong2*)(rp + 2);
            ulonglong2 p2 = *(const ulonglong2*)(rp + 4);
            unsigned long long v[6] = {p0.x, p0.y, p1.x, p1.y, p2.x, p2.y};
            #pragma unroll
            for (int ky = 0; ky < 5; ky++) {
                const int oy = r - ky;
                if (oy < 0 || oy > 3) continue;   // compile-time pruned
                #pragma unroll
                for (int kx = 0; kx < 5; kx++) {
                    #pragma unroll
                    for (int co = 0; co < 2; co++) {
                        unsigned long long wp =
                            g_wc[woff + ((co * CI + ci) * 5 + ky) * 5 + kx];
                        ffma2(acc[oy][0][co], wp, v[kx]);
                        ffma2(acc[oy][1][co], wp, v[kx + 1]);
                    }
                }
            }
        }
    }

    const float2 brs0 = g_brs[brsoff];
    const float2 brs1 = g_brs[brsoff + 1];
    const int ox0 = blockIdx.x * 32 + 2 * tx;
    const int oy0 = blockIdx.y * 64 + 4 * ty;

    float xov[4][2][2], cov[4][2][2];
    #pragma unroll
    for (int oy = 0; oy < 4; oy++)
        #pragma unroll
        for (int xp = 0; xp < 2; xp++)
            #pragma unroll
            for (int co = 0; co < 2; co++) {
                float2 u = unpk(acc[oy][xp][co]);
                float bx = co ? brs1.x : brs0.x;
                float rs = co ? brs1.y : brs0.y;
                xov[oy][xp][co] = __fdividef(u.x, u.y + NEPS) + bx;
                cov[oy][xp][co] = u.y * rs;
            }

    if (ox0 < W) {
        #pragma unroll
        for (int oy = 0; oy < 4; oy++) {
            int y = oy0 + oy;
            if (y < H) {
                #pragma unroll
                for (int co = 0; co < 2; co++) {
                    int o = ((b * 2 + co) * H + y) * W + ox0;
                    *(float2*)&xout[o] = make_float2(xov[oy][0][co], xov[oy][1][co]);
                    *(float2*)&cout[o] = make_float2(cov[oy][0][co], cov[oy][1][co]);
                }
            }
        }
        if (POOL) {
            #pragma unroll
            for (int pb = 0; pb < 2; pb++) {
                int y = oy0 + 2 * pb;
                if (y >= H) continue;
                #pragma unroll
                for (int co = 0; co < 2; co++) {
                    float bc = cov[2*pb][0][co], bx = xov[2*pb][0][co];
                    if (cov[2*pb][1][co]   > bc) { bc = cov[2*pb][1][co];   bx = xov[2*pb][1][co];   }
                    if (cov[2*pb+1][0][co] > bc) { bc = cov[2*pb+1][0][co]; bx = xov[2*pb+1][0][co]; }
                    if (cov[2*pb+1][1][co] > bc) { bc = cov[2*pb+1][1][co]; bx = xov[2*pb+1][1][co]; }
                    int o = ((b * 2 + co) * (H >> 1) + (y >> 1)) * (W >> 1) + (ox0 >> 1);
                    cpool[o] = bc * 0.25f;
                    xpool[o] = bx;
                }
            }
        }
    }
}

// ---------------------------------------------------------------------------
// concat(2ch, 2ch) -> 3x3 navg (CI=4). Nearest-up fused via >>shift in loader.
// Thread micro-tile 2x2; block 32x32 outputs.
// FINAL: fuse trailing 1x1 navg (w4,b4); outputs 1ch x/c planes into d_out.
// ---------------------------------------------------------------------------
template<bool FINAL>
__global__ void __launch_bounds__(256, 2)
navg3cat(const float* __restrict__ x1, const float* __restrict__ c1, int sh1,
         const float* __restrict__ x2, const float* __restrict__ c2, int sh2,
         int woff, int brsoff,
         float* __restrict__ xout, float* __restrict__ cout,
         int H, int W)
{
    constexpr int CI = 4, SH = 34, SW = 34;
    __shared__ __align__(16) unsigned long long sm[CI][SH][SW];

    const int tid = threadIdx.x;
    const int tx  = tid & 15, ty = tid >> 4;
    const int b   = blockIdx.z;
    const int gx0 = blockIdx.x * 32 - 1;
    const int gy0 = blockIdx.y * 32 - 1;

    float2* smf = (float2*)sm;
    for (int i = tid; i < CI * SH * SW; i += 256) {
        int ci = i / (SH * SW), rem = i % (SH * SW);
        int ly = rem / SW, lx = rem % SW;
        int gy = gy0 + ly, gx = gx0 + lx;
        const float* xs = (ci < 2) ? x1 : x2;
        const float* cs = (ci < 2) ? c1 : c2;
        int sh = (ci < 2) ? sh1 : sh2;
        int cc = ci & 1;
        float cv = 0.f, xv = 0.f;
        if ((unsigned)gy < (unsigned)H && (unsigned)gx < (unsigned)W) {
            int Hs = H >> sh, Ws = W >> sh;
            int o = ((b * 2 + cc) * Hs + (gy >> sh)) * Ws + (gx >> sh);
            cv = cs[o];
            xv = xs[o];
        }
        smf[i] = make_float2(xv * cv, cv);
    }
    __syncthreads();

    unsigned long long acc[2][2][2];
    #pragma unroll
    for (int i = 0; i < 2; i++)
        #pragma unroll
        for (int j = 0; j < 2; j++)
            #pragma unroll
            for (int k = 0; k < 2; k++) acc[i][j][k] = 0ULL;

    #pragma unroll
    for (int ci = 0; ci < 4; ci++) {
        #pragma unroll
        for (int r = 0; r < 4; r++) {
            const unsigned long long* rp = &sm[ci][2 * ty + r][2 * tx];
            ulonglong2 p0 = *(const ulonglong2*)rp;
            ulonglong2 p1 = *(const ulonglong2*)(rp + 2);
            unsigned long long v[4] = {p0.x, p0.y, p1.x, p1.y};
            #pragma unroll
            for (int ky = 0; ky < 3; ky++) {
                const int oy = r - ky;
                if (oy < 0 || oy > 1) continue;
                #pragma unroll
                for (int kx = 0; kx < 3; kx++) {
                    #pragma unroll
                    for (int co = 0; co < 2; co++) {
                        unsigned long long wp =
                            g_wc[woff + ((co * 4 + ci) * 3 + ky) * 3 + kx];
                        ffma2(acc[oy][0][co], wp, v[kx]);
                        ffma2(acc[oy][1][co], wp, v[kx + 1]);
                    }
                }
            }
        }
    }

    const float2 brs0 = g_brs[brsoff];
    const float2 brs1 = g_brs[brsoff + 1];
    const int ox0 = blockIdx.x * 32 + 2 * tx;
    const int oy0 = blockIdx.y * 32 + 2 * ty;

    float w40 = 0.f, w41 = 0.f; float2 brs4 = make_float2(0.f, 0.f);
    if (FINAL) {
        w40 = unpk(g_wc[466]).x;
        w41 = unpk(g_wc[467]).x;
        brs4 = g_brs[12];
    }

    if (ox0 < W) {
        #pragma unroll
        for (int oy = 0; oy < 2; oy++) {
            int y = oy0 + oy;
            if (y >= H) continue;

            float xo_[2][2], co_[2][2];   // [xp][co]
            #pragma unroll
            for (int xp = 0; xp < 2; xp++)
                #pragma unroll
                for (int co = 0; co < 2; co++) {
                    float2 u = unpk(acc[oy][xp][co]);
                    float bx = co ? brs1.x : brs0.x;
                    float rs = co ? brs1.y : brs0.y;
                    xo_[xp][co] = __fdividef(u.x, u.y + NEPS) + bx;
                    co_[xp][co] = u.y * rs;
                }

            if (FINAL) {
                float xf[2], cf[2];
                #pragma unroll
                for (int xp = 0; xp < 2; xp++) {
                    float a4 = w40 * co_[xp][0] + w41 * co_[xp][1];
                    float xn = w40 * (xo_[xp][0] * co_[xp][0]) +
                               w41 * (xo_[xp][1] * co_[xp][1]);
                    xf[xp] = __fdividef(xn, a4 + NEPS) + brs4.x;
                    cf[xp] = a4 * brs4.y;
                }
                int o = (b * H + y) * W + ox0;
                *(float2*)&xout[o] = make_float2(xf[0], xf[1]);
                *(float2*)&cout[o] = make_float2(cf[0], cf[1]);
            } else {
                #pragma unroll
                for (int co = 0; co < 2; co++) {
                    int o = ((b * 2 + co) * H + y) * W + ox0;
                    *(float2*)&xout[o] = make_float2(xo_[0][co], xo_[1][co]);
                    *(float2*)&cout[o] = make_float2(co_[0][co], co_[1][co]);
                }
            }
        }
    }
}

// ---------------------------------------------------------------------------
extern "C" void kernel_launch(void* const* d_in, const int* in_sizes, int n_in,
                              void* d_out, int out_size)
{
    (void)in_sizes; (void)n_in; (void)out_size;
    const float* x0  = (const float*)d_in[0];
    const float* c0  = (const float*)d_in[1];
    const float* w1  = (const float*)d_in[2];
    const float* w2  = (const float*)d_in[3];
    const float* w3  = (const float*)d_in[4];
    const float* w4  = (const float*)d_in[5];
    const float* w34 = (const float*)d_in[6];
    const float* w23 = (const float*)d_in[7];
    const float* w12 = (const float*)d_in[8];
    const float* b1  = (const float*)d_in[9];
    const float* b2  = (const float*)d_in[10];
    const float* b3  = (const float*)d_in[11];
    const float* b4  = (const float*)d_in[12];
    const float* b34 = (const float*)d_in[13];
    const float* b23 = (const float*)d_in[14];
    const float* b12 = (const float*)d_in[15];
    float* outp = (float*)d_out;

    float *fx_a, *fc_a, *fx_b, *fc_b;
    float *hx_a, *hc_a, *hx_b, *hc_b;
    float *qx_a, *qc_a, *qx_b, *qc_b;
    float *ex_a, *ec_a, *ex_b, *ec_b;
    cudaGetSymbolAddress((void**)&fx_a, g_fx_a);
    cudaGetSymbolAddress((void**)&fc_a, g_fc_a);
    cudaGetSymbolAddress((void**)&fx_b, g_fx_b);
    cudaGetSymbolAddress((void**)&fc_b, g_fc_b);
    cudaGetSymbolAddress((void**)&hx_a, g_hx_a);
    cudaGetSymbolAddress((void**)&hc_a, g_hc_a);
    cudaGetSymbolAddress((void**)&hx_b, g_hx_b);
    cudaGetSymbolAddress((void**)&hc_b, g_hc_b);
    cudaGetSymbolAddress((void**)&qx_a, g_qx_a);
    cudaGetSymbolAddress((void**)&qc_a, g_qc_a);
    cudaGetSymbolAddress((void**)&qx_b, g_qx_b);
    cudaGetSymbolAddress((void**)&qc_b, g_qc_b);
    cudaGetSymbolAddress((void**)&ex_a, g_ex_a);
    cudaGetSymbolAddress((void**)&ec_a, g_ec_a);
    cudaGetSymbolAddress((void**)&ex_b, g_ex_b);
    cudaGetSymbolAddress((void**)&ec_b, g_ec_b);

    void* wc_ptr;     cudaGetSymbolAddress(&wc_ptr, g_wc);
    void* stage_ptr;  cudaGetSymbolAddress(&stage_ptr, g_wstage);

    prep_kernel<<<1, 512>>>(w1, w2, w3, w34, w23, w12, w4,
                            b1, b2, b3, b34, b23, b12, b4);
    cudaMemcpyAsync(wc_ptr, stage_ptr, 468 * sizeof(unsigned long long),
                    cudaMemcpyDeviceToDevice, 0);

    auto g5 = [](int W, int H) { return dim3((W + 31) / 32, (H + 63) / 64, BB); };
    auto g3 = [](int W, int H) { return dim3((W + 31) / 32, (H + 31) / 32, BB); };

    // L1: navg(w1, c0, x0)  full, CI=1
    navg5<1, false><<<g5(640, 512), 256>>>(x0, c0, 0, 0,
        fx_a, fc_a, nullptr, nullptr, 512, 640);
    // L2: navg(w2)  full
    navg5<2, false><<<g5(640, 512), 256>>>(fx_a, fc_a, 50, 2,
        fx_b, fc_b, nullptr, nullptr, 512, 640);
    // L3: navg(w3) -> (x1,c1) + fused pool -> half
    navg5<2, true><<<g5(640, 512), 256>>>(fx_b, fc_b, 150, 4,
        fx_a, fc_a, hx_a, hc_a, 512, 640);
    // L5: navg(w2)  half
    navg5<2, false><<<g5(320, 256), 256>>>(hx_a, hc_a, 50, 2,
        hx_b, hc_b, nullptr, nullptr, 256, 320);
    // L6: navg(w3) -> (x2_ds,c2_ds) + pool -> quarter
    navg5<2, true><<<g5(320, 256), 256>>>(hx_b, hc_b, 150, 4,
        hx_a, hc_a, qx_a, qc_a, 256, 320);
    // L8: navg(w2) -> (x3_ds,c3_ds) + pool -> eighth
    navg5<2, true><<<g5(160, 128), 256>>>(qx_a, qc_a, 50, 2,
        qx_b, qc_b, ex_a, ec_a, 128, 160);
    // L10: navg(w2) -> (x4_ds,c4_ds)  eighth
    navg5<2, false><<<g5(80, 64), 256>>>(ex_a, ec_a, 50, 2,
        ex_b, ec_b, nullptr, nullptr, 64, 80);
    // L12: navg(w34, cat(c3_ds, up2(c4_ds)))  quarter
    navg3cat<false><<<g3(160, 128), 256>>>(qx_b, qc_b, 0, ex_b, ec_b, 1,
        250, 6, qx_a, qc_a, 128, 160);
    // L14: navg(w23, cat(c2_ds, up2(c34_ds)))  half
    navg3cat<false><<<g3(320, 256), 256>>>(hx_a, hc_a, 0, qx_a, qc_a, 1,
        322, 8, hx_b, hc_b, 256, 320);
    // L16+L17: navg(w12, cat(up2(c23), c1)) + fused 1x1 navg(w4) -> d_out
    navg3cat<true><<<g3(640, 512), 256>>>(hx_b, hc_b, 1, fx_a, fc_a, 0,
        394, 10, outp, outp + (size_t)BB * H0 * W0, 512, 640);
}